// round 3
// baseline (speedup 1.0000x reference)
#include <cuda_runtime.h>
#include <math.h>

#define BB 64
#define SS 4
#define LL 64
#define CC 32
#define HH 4
#define DD 8
#define CPD 16
#define LN_EPS 1e-5f

__device__ float g_xbuf[BB * LL * SS * CC];   // (b,l,s,c) after row attention
__device__ float g_m[BB * LL * CC];           // (b,l,c) track-mean
__device__ float g_u[BB * LL * CPD * CC];     // u[b,i,p,c2] = m_i^T W_p  (8MB)
__device__ float g_nrm[BB * LL];              // |m_i|
__device__ float g_we[96];                    // Win · ew  per row
__device__ float g_wcR[96 * 64];              // row-major:  [r][i] = Win_r·(eb+pos_i)+b_r
__device__ float g_wcT[64 * 96];              // token-major [i][r]

__device__ __forceinline__ float dot4(float4 a, float4 b) {
    return a.x * b.x + a.y * b.y + a.z * b.z + a.w * b.w;
}

// ---------------------------------------------------------------------------
// k_pre: position-constant projection tables (row attention is rank-1 in data)
// grid=96 (r = qkv row), block=64 (i = token)
// ---------------------------------------------------------------------------
__global__ __launch_bounds__(64)
void k_pre(const float* __restrict__ Win, const float* __restrict__ bin,
           const float* __restrict__ eb,  const float* __restrict__ pos,
           const float* __restrict__ ew)
{
    const int r = blockIdx.x;
    const int i = threadIdx.x;
    float a = bin[r];
    #pragma unroll
    for (int c = 0; c < CC; c++)
        a += Win[r * CC + c] * (eb[c] + pos[i * CC + c]);
    g_wcR[r * 64 + i] = a;
    g_wcT[i * 96 + r] = a;
    if (i == 0) {
        float e = 0.f;
        #pragma unroll
        for (int c = 0; c < CC; c++) e += Win[r * CC + c] * ew[c];
        g_we[r] = e;
    }
}

// ---------------------------------------------------------------------------
// Kernel 1: row MHA + residual LN.  grid = B*S*2 = 512 (i-half split),
// block = 256: warp w -> h=w&3, jh=w>>2 ; lane -> i_local
// ---------------------------------------------------------------------------
__global__ __launch_bounds__(256)
void k_row_attn(const float* __restrict__ ctcf, const float* __restrict__ hac,
                const float* __restrict__ me1,  const float* __restrict__ me3,
                const float* __restrict__ ew,   const float* __restrict__ eb,
                const float* __restrict__ pos,
                const float* __restrict__ Wout, const float* __restrict__ bout,
                const float* __restrict__ lng,  const float* __restrict__ lnb)
{
    __shared__ __align__(16) float sk[LL * 36];
    __shared__ __align__(16) float sv[LL * 36];
    __shared__ float so[32 * 33];
    __shared__ float spos[32 * 33];
    __shared__ float sWout[CC * CC];
    __shared__ float pacc[HH][32][9];
    __shared__ float pmu[8][32], pvar[8][32];
    __shared__ float ssval[LL];
    __shared__ float sbo[CC], sg[CC], sb2[CC], sew[CC], seb[CC];

    const int blk = blockIdx.x;
    const int b = blk >> 3;
    const int s = (blk >> 1) & 3;
    const int ihalf = blk & 1;
    const int tid = threadIdx.x;
    const int w = tid >> 5;
    const int lane = tid & 31;
    const int h = w & 3;         // warp-uniform
    const int jh = w >> 2;       // warp-uniform
    const int i = ihalf * 32 + lane;

    const float* sig = (s == 0) ? ctcf : (s == 1) ? hac : (s == 2) ? me1 : me3;
    if (tid < 64) ssval[tid] = sig[b * LL + tid];
    for (int t = tid; t < CC * CC; t += 256) sWout[t] = Wout[t];
    if (tid < CC) {
        sbo[tid] = bout[tid]; sg[tid] = lng[tid]; sb2[tid] = lnb[tid];
        sew[tid] = ew[tid];  seb[tid] = eb[tid];
    }
    for (int t = tid; t < 1024; t += 256)
        spos[(t >> 5) * 33 + (t & 31)] = pos[ihalf * 1024 + t];
    __syncthreads();

    // fill k,v for all 64 tokens: 1 FMA per element (rank-1 decomposition)
    for (int t = tid; t < 2048; t += 256) {
        const int j = t >> 5, d = t & 31;
        const float sj = ssval[j];
        sk[j * 36 + d] = sj * g_we[32 + d] + g_wcT[j * 96 + 32 + d];
        sv[j * 36 + d] = sj * g_we[64 + d] + g_wcT[j * 96 + 64 + d];
    }
    const float sval_i = ssval[i];
    float q[DD];
    #pragma unroll
    for (int d = 0; d < DD; d++)
        q[d] = sval_i * g_we[h * DD + d] + g_wcR[(h * DD + d) * 64 + i];
    __syncthreads();

    // attention over this thread's j-half
    const float scale = 0.3535533905932738f;
    float se = 0.f;
    float acc[DD];
    #pragma unroll
    for (int d = 0; d < DD; d++) acc[d] = 0.f;
    const int j0 = jh * 32;
    #pragma unroll 4
    for (int jj = 0; jj < 32; jj++) {
        const int j = j0 + jj;
        float4 k0 = *(const float4*)&sk[j * 36 + h * DD];
        float4 k1 = *(const float4*)&sk[j * 36 + h * DD + 4];
        float a = q[0]*k0.x + q[1]*k0.y + q[2]*k0.z + q[3]*k0.w
                + q[4]*k1.x + q[5]*k1.y + q[6]*k1.z + q[7]*k1.w;
        float p = __expf(a * scale);
        se += p;
        float4 v0 = *(const float4*)&sv[j * 36 + h * DD];
        float4 v1 = *(const float4*)&sv[j * 36 + h * DD + 4];
        acc[0] += p * v0.x; acc[1] += p * v0.y; acc[2] += p * v0.z; acc[3] += p * v0.w;
        acc[4] += p * v1.x; acc[5] += p * v1.y; acc[6] += p * v1.z; acc[7] += p * v1.w;
    }
    if (jh == 1) {
        #pragma unroll
        for (int d = 0; d < DD; d++) pacc[h][lane][d] = acc[d];
        pacc[h][lane][8] = se;
    }
    __syncthreads();
    if (jh == 0) {
        se += pacc[h][lane][8];
        #pragma unroll
        for (int d = 0; d < DD; d++) acc[d] += pacc[h][lane][d];
        const float inv = 1.f / se;
        #pragma unroll
        for (int d = 0; d < DD; d++) so[lane * 33 + h * DD + d] = acc[d] * inv;
    }
    __syncthreads();

    // out-proj: 4 channels per thread, cb = h*8 + jh*4
    float orow[CC];
    #pragma unroll
    for (int k = 0; k < CC; k++) orow[k] = so[lane * 33 + k];
    const int cb = h * DD + jh * 4;
    float y[4];
    float part = 0.f;
    #pragma unroll
    for (int cc = 0; cc < 4; cc++) {
        const int c = cb + cc;
        float a = sbo[c];
        #pragma unroll
        for (int k = 0; k < CC; k++) a += orow[k] * sWout[c * CC + k];
        const float x = sval_i * sew[c] + seb[c] + spos[lane * 33 + c];
        y[cc] = a + x;
        part += y[cc];
    }
    pmu[w][lane] = part;
    __syncthreads();
    float mu = 0.f;
    #pragma unroll
    for (int t = 0; t < 8; t++) mu += pmu[t][lane];
    mu *= (1.f / CC);
    float vp = 0.f;
    #pragma unroll
    for (int cc = 0; cc < 4; cc++) { float d = y[cc] - mu; vp += d * d; }
    pvar[w][lane] = vp;
    __syncthreads();
    float var = 0.f;
    #pragma unroll
    for (int t = 0; t < 8; t++) var += pvar[t][lane];
    var *= (1.f / CC);
    const float rs = rsqrtf(var + LN_EPS);

    float4 o4;
    o4.x = (y[0] - mu) * rs * sg[cb + 0] + sb2[cb + 0];
    o4.y = (y[1] - mu) * rs * sg[cb + 1] + sb2[cb + 1];
    o4.z = (y[2] - mu) * rs * sg[cb + 2] + sb2[cb + 2];
    o4.w = (y[3] - mu) * rs * sg[cb + 3] + sb2[cb + 3];
    *(float4*)&g_xbuf[((b * LL + i) * SS + s) * CC + cb] = o4;
}

// ---------------------------------------------------------------------------
// Kernel 2: column MHA (seq=4) + LN + mean over S.
// grid = B*8 = 512 (8 l's/block), block = 256: warp w -> h=w&3, role sp=w>>2
// lane = token tk = ll*4 + s
// ---------------------------------------------------------------------------
__global__ __launch_bounds__(256)
void k_col_attn(const float* __restrict__ Win,  const float* __restrict__ bin,
                const float* __restrict__ Wout, const float* __restrict__ bout,
                const float* __restrict__ lng,  const float* __restrict__ lnb)
{
    __shared__ float sx[32 * 33];
    __shared__ float sk[32 * 33];
    __shared__ float sv[32 * 33];
    __shared__ float so[32 * 33];
    __shared__ float sWin[96 * CC];
    __shared__ float sWout[CC * CC];
    __shared__ float sbin[96];
    __shared__ float sbo[CC], sg[CC], sb2[CC];
    __shared__ float pmu[8][32], pvar[8][32];

    const int blk = blockIdx.x;
    const int b = blk >> 3;
    const int lg = blk & 7;
    const int tid = threadIdx.x;
    const int w = tid >> 5;
    const int tk = tid & 31;
    const int h = w & 3;       // warp-uniform
    const int sp = w >> 2;     // warp-uniform role

    const int gb = (b * 64 + lg * 8) * SS * CC;  // 32 contiguous rows
    for (int t = tid; t < 1024; t += 256)
        sx[(t >> 5) * 33 + (t & 31)] = g_xbuf[gb + t];
    for (int t = tid; t < 96 * CC; t += 256) sWin[t] = Win[t];
    for (int t = tid; t < CC * CC; t += 256) sWout[t] = Wout[t];
    if (tid < 96) sbin[tid] = bin[tid];
    if (tid < CC) { sbo[tid] = bout[tid]; sg[tid] = lng[tid]; sb2[tid] = lnb[tid]; }
    __syncthreads();

    float xr[CC];
    #pragma unroll
    for (int c = 0; c < CC; c++) xr[c] = sx[tk * 33 + c];

    float q[DD];
    if (sp == 0) {
        #pragma unroll
        for (int d = 0; d < DD; d++) {
            const int r = h * DD + d;
            float a = sbin[r];
            #pragma unroll
            for (int c = 0; c < CC; c++) a += xr[c] * sWin[r * CC + c];
            q[d] = a;
        }
    } else {
        #pragma unroll
        for (int d = 0; d < DD; d++) {
            const int r = CC + h * DD + d;
            float a = sbin[r];
            #pragma unroll
            for (int c = 0; c < CC; c++) a += xr[c] * sWin[r * CC + c];
            sk[tk * 33 + h * DD + d] = a;
        }
        #pragma unroll
        for (int d = 0; d < DD; d++) {
            const int r = 2 * CC + h * DD + d;
            float a = sbin[r];
            #pragma unroll
            for (int c = 0; c < CC; c++) a += xr[c] * sWin[r * CC + c];
            sv[tk * 33 + h * DD + d] = a;
        }
    }
    __syncthreads();

    if (sp == 0) {
        const float scale = 0.3535533905932738f;
        const int base = tk & ~3;
        float se = 0.f;
        float acc[DD];
        #pragma unroll
        for (int d = 0; d < DD; d++) acc[d] = 0.f;
        #pragma unroll
        for (int j = 0; j < SS; j++) {
            float a = 0.f;
            #pragma unroll
            for (int d = 0; d < DD; d++) a += q[d] * sk[(base + j) * 33 + h * DD + d];
            float p = __expf(a * scale);
            se += p;
            #pragma unroll
            for (int d = 0; d < DD; d++) acc[d] += p * sv[(base + j) * 33 + h * DD + d];
        }
        const float inv = 1.f / se;
        #pragma unroll
        for (int d = 0; d < DD; d++) so[tk * 33 + h * DD + d] = acc[d] * inv;
    }
    __syncthreads();

    float orow[CC];
    #pragma unroll
    for (int k = 0; k < CC; k++) orow[k] = so[tk * 33 + k];
    const int cb = h * DD + sp * 4;
    float y[4];
    float part = 0.f;
    #pragma unroll
    for (int cc = 0; cc < 4; cc++) {
        const int c = cb + cc;
        float a = sbo[c];
        #pragma unroll
        for (int k = 0; k < CC; k++) a += orow[k] * sWout[c * CC + k];
        y[cc] = a + sx[tk * 33 + c];   // residual from smem (no dyn reg index)
        part += y[cc];
    }
    pmu[w][tk] = part;
    __syncthreads();
    float mu = 0.f;
    #pragma unroll
    for (int t = 0; t < 8; t++) mu += pmu[t][tk];
    mu *= (1.f / CC);
    float vp = 0.f;
    #pragma unroll
    for (int cc = 0; cc < 4; cc++) { float d = y[cc] - mu; vp += d * d; }
    pvar[w][tk] = vp;
    __syncthreads();
    float var = 0.f;
    #pragma unroll
    for (int t = 0; t < 8; t++) var += pvar[t][tk];
    var *= (1.f / CC);
    const float rs = rsqrtf(var + LN_EPS);

    // LN output then mean over the 4 tracks (s = tk&3 are adjacent lanes)
    float m0[4];
    #pragma unroll
    for (int cc = 0; cc < 4; cc++) {
        float v = (y[cc] - mu) * rs * sg[cb + cc] + sb2[cb + cc];
        v += __shfl_xor_sync(0xffffffffu, v, 1);
        v += __shfl_xor_sync(0xffffffffu, v, 2);
        m0[cc] = v * 0.25f;
    }
    if ((tk & 3) == 0) {
        const int l = lg * 8 + (tk >> 2);
        *(float4*)&g_m[(b * LL + l) * CC + cb] = make_float4(m0[0], m0[1], m0[2], m0[3]);
    }
}

// ---------------------------------------------------------------------------
// Kernel 3a: u[b,i,p,c2] = sum_c1 m[b,i,c1] * Wp[p,c1,c2]  + norms
// grid = B*4 = 256 (16 i's/block), block = 256
// ---------------------------------------------------------------------------
__global__ __launch_bounds__(256)
void k_pair_u(const float* __restrict__ Wp)
{
    __shared__ float sm16[16 * 33];
    const int b  = blockIdx.x >> 2;
    const int qi = blockIdx.x & 3;
    const int tid = threadIdx.x;

    for (int t = tid; t < 512; t += 256)
        sm16[(t >> 5) * 33 + (t & 31)] = g_m[b * (LL * CC) + qi * 512 + t];
    __syncthreads();

    if (tid < 16) {
        float a = 0.f;
        #pragma unroll
        for (int c = 0; c < CC; c++) { float v = sm16[tid * 33 + c]; a += v * v; }
        g_nrm[b * LL + qi * 16 + tid] = sqrtf(a);
    }

    for (int t = tid; t < 8192; t += 256) {
        const int il = t >> 9;
        const int k  = t & 511;
        const int p  = k >> 5;
        const int c2 = k & 31;
        float a = 0.f;
        #pragma unroll
        for (int c1 = 0; c1 < CC; c1++)
            a += sm16[il * 33 + c1] * Wp[p * (CC * CC) + c1 * CC + c2];
        g_u[(b * LL + qi * 16 + il) * 512 + k] = a;
    }
}

// ---------------------------------------------------------------------------
// Kernel 3b: feat[b,i,j,p] = u[i]·m[j]/max(|m_i||m_j|,1e-6)+bp -> LN -> SiLU
// grid = B*16 = 1024 (4 i's/block), block = 256: thread = one (i,j) pair
// ---------------------------------------------------------------------------
__global__ __launch_bounds__(256)
void k_pair_out(const float* __restrict__ bp, const float* __restrict__ png,
                const float* __restrict__ pnb, float* __restrict__ out)
{
    __shared__ float sm[LL * 33];
    __shared__ __align__(16) float su4[4 * 512];
    __shared__ float snrm[LL];
    __shared__ float sbp[CPD], sg[CPD], sb[CPD];

    const int b  = blockIdx.x >> 4;
    const int ch = blockIdx.x & 15;
    const int tid = threadIdx.x;

    for (int t = tid; t < 2048; t += 256) {
        sm[(t >> 5) * 33 + (t & 31)] = g_m[b * (LL * CC) + t];
        su4[t] = g_u[(b * LL + ch * 4) * 512 + t];
    }
    if (tid < 64) snrm[tid] = g_nrm[b * LL + tid];
    if (tid < CPD) { sbp[tid] = bp[tid]; sg[tid] = png[tid]; sb[tid] = pnb[tid]; }
    __syncthreads();

    const int il = tid >> 6;      // warp-uniform
    const int j  = tid & 63;
    const int i  = ch * 4 + il;
    const float inv = 1.f / fmaxf(snrm[i] * snrm[j], 1e-6f);

    float mjr[CC];
    #pragma unroll
    for (int c = 0; c < CC; c++) mjr[c] = sm[j * 33 + c];   // stride-33: conflict-free

    float f[CPD];
    float mu = 0.f;
    #pragma unroll
    for (int p = 0; p < CPD; p++) {
        const float4* up = (const float4*)&su4[il * 512 + p * CC];
        float a = 0.f;
        #pragma unroll
        for (int c4 = 0; c4 < 8; c4++)
            a += up[c4].x * mjr[c4*4] + up[c4].y * mjr[c4*4+1]
               + up[c4].z * mjr[c4*4+2] + up[c4].w * mjr[c4*4+3];
        a = a * inv + sbp[p];
        f[p] = a;
        mu += a;
    }
    mu *= (1.f / CPD);
    float var = 0.f;
    #pragma unroll
    for (int p = 0; p < CPD; p++) { float d = f[p] - mu; var += d * d; }
    var *= (1.f / CPD);
    const float rs = rsqrtf(var + LN_EPS);
    #pragma unroll
    for (int p = 0; p < CPD; p++) {
        float xn = (f[p] - mu) * rs * sg[p] + sb[p];
        float yv = xn / (1.f + __expf(-xn));
        out[((b * CPD + p) * LL + i) * LL + j] = yv;
    }
}

// ---------------------------------------------------------------------------
extern "C" void kernel_launch(void* const* d_in, const int* in_sizes, int n_in,
                              void* d_out, int out_size)
{
    const float* ctcf = (const float*)d_in[0];
    const float* hac  = (const float*)d_in[1];
    const float* me1  = (const float*)d_in[2];
    const float* me3  = (const float*)d_in[3];
    const float* ew   = (const float*)d_in[4];
    const float* eb   = (const float*)d_in[5];
    const float* pos  = (const float*)d_in[6];
    const float* riw  = (const float*)d_in[7];
    const float* rib  = (const float*)d_in[8];
    const float* row_ = (const float*)d_in[9];
    const float* rob  = (const float*)d_in[10];
    const float* rlg  = (const float*)d_in[11];
    const float* rlb  = (const float*)d_in[12];
    const float* ciw  = (const float*)d_in[13];
    const float* cib  = (const float*)d_in[14];
    const float* cow  = (const float*)d_in[15];
    const float* cob  = (const float*)d_in[16];
    const float* clg  = (const float*)d_in[17];
    const float* clb  = (const float*)d_in[18];
    const float* pw   = (const float*)d_in[19];
    const float* pb   = (const float*)d_in[20];
    const float* plg  = (const float*)d_in[21];
    const float* plb  = (const float*)d_in[22];
    float* out = (float*)d_out;

    k_pre<<<96, 64>>>(riw, rib, eb, pos, ew);
    k_row_attn<<<BB * SS * 2, 256>>>(ctcf, hac, me1, me3, ew, eb, pos,
                                     row_, rob, rlg, rlb);
    k_col_attn<<<BB * 8, 256>>>(ciw, cib, cow, cob, clg, clb);
    k_pair_u<<<BB * 4, 256>>>(pw);
    k_pair_out<<<BB * 16, 256>>>(pb, plg, plb, out);
}

// round 4
// speedup vs baseline: 1.2876x; 1.2876x over previous
#include <cuda_runtime.h>
#include <math.h>

#define BB 64
#define SS 4
#define LL 64
#define CC 32
#define HH 4
#define DD 8
#define CPD 16
#define LN_EPS 1e-5f

__device__ float g_xbuf[BB * LL * SS * CC];   // (b,l,s,c) after row attention
__device__ float g_m[BB * LL * CC];           // (b,l,c) track-mean
__device__ float g_we[96];                    // Win · ew  per row
__device__ float g_wcR[96 * 64];              // [r][i] = Win_r·(eb+pos_i)+b_r
__device__ float g_wcT[64 * 96];              // token-major [i][r]

// ---------------------------------------------------------------------------
// k_pre: position-constant projection tables (row attention is rank-1 in data)
// ---------------------------------------------------------------------------
__global__ __launch_bounds__(64)
void k_pre(const float* __restrict__ Win, const float* __restrict__ bin,
           const float* __restrict__ eb,  const float* __restrict__ pos,
           const float* __restrict__ ew)
{
    const int r = blockIdx.x;
    const int i = threadIdx.x;
    float a = bin[r];
    #pragma unroll
    for (int c = 0; c < CC; c++)
        a += Win[r * CC + c] * (eb[c] + pos[i * CC + c]);
    g_wcR[r * 64 + i] = a;
    g_wcT[i * 96 + r] = a;
    if (i == 0) {
        float e = 0.f;
        #pragma unroll
        for (int c = 0; c < CC; c++) e += Win[r * CC + c] * ew[c];
        g_we[r] = e;
    }
}

// ---------------------------------------------------------------------------
// Kernel 1: row MHA + residual LN.  grid = B*S*2 = 512 (i-half split),
// block = 256: warp w -> h=w&3, jh=w>>2 ; lane -> i_local
// ---------------------------------------------------------------------------
__global__ __launch_bounds__(256)
void k_row_attn(const float* __restrict__ ctcf, const float* __restrict__ hac,
                const float* __restrict__ me1,  const float* __restrict__ me3,
                const float* __restrict__ ew,   const float* __restrict__ eb,
                const float* __restrict__ pos,
                const float* __restrict__ Wout, const float* __restrict__ bout,
                const float* __restrict__ lng,  const float* __restrict__ lnb)
{
    __shared__ __align__(16) float sk[LL * 36];
    __shared__ __align__(16) float sv[LL * 36];
    __shared__ float so[32 * 33];
    __shared__ float spos[32 * 33];
    __shared__ float sWout[CC * CC];
    __shared__ float pacc[HH][32][9];
    __shared__ float pmu[8][32], pvar[8][32];
    __shared__ float ssval[LL];
    __shared__ float sbo[CC], sg[CC], sb2[CC], sew[CC], seb[CC];

    const int blk = blockIdx.x;
    const int b = blk >> 3;
    const int s = (blk >> 1) & 3;
    const int ihalf = blk & 1;
    const int tid = threadIdx.x;
    const int w = tid >> 5;
    const int lane = tid & 31;
    const int h = w & 3;
    const int jh = w >> 2;
    const int i = ihalf * 32 + lane;

    const float* sig = (s == 0) ? ctcf : (s == 1) ? hac : (s == 2) ? me1 : me3;
    if (tid < 64) ssval[tid] = sig[b * LL + tid];
    for (int t = tid; t < CC * CC; t += 256) sWout[t] = Wout[t];
    if (tid < CC) {
        sbo[tid] = bout[tid]; sg[tid] = lng[tid]; sb2[tid] = lnb[tid];
        sew[tid] = ew[tid];  seb[tid] = eb[tid];
    }
    for (int t = tid; t < 1024; t += 256)
        spos[(t >> 5) * 33 + (t & 31)] = pos[ihalf * 1024 + t];
    __syncthreads();

    // fill k,v for all 64 tokens: 1 FMA/element (rank-1 decomposition)
    for (int t = tid; t < 2048; t += 256) {
        const int j = t >> 5, d = t & 31;
        const float sj = ssval[j];
        sk[j * 36 + d] = sj * g_we[32 + d] + g_wcT[j * 96 + 32 + d];
        sv[j * 36 + d] = sj * g_we[64 + d] + g_wcT[j * 96 + 64 + d];
    }
    const float sval_i = ssval[i];
    float q[DD];
    #pragma unroll
    for (int d = 0; d < DD; d++)
        q[d] = sval_i * g_we[h * DD + d] + g_wcR[(h * DD + d) * 64 + i];
    __syncthreads();

    const float scale = 0.3535533905932738f;
    float se = 0.f;
    float acc[DD];
    #pragma unroll
    for (int d = 0; d < DD; d++) acc[d] = 0.f;
    const int j0 = jh * 32;
    #pragma unroll 4
    for (int jj = 0; jj < 32; jj++) {
        const int j = j0 + jj;
        float4 k0 = *(const float4*)&sk[j * 36 + h * DD];
        float4 k1 = *(const float4*)&sk[j * 36 + h * DD + 4];
        float a = q[0]*k0.x + q[1]*k0.y + q[2]*k0.z + q[3]*k0.w
                + q[4]*k1.x + q[5]*k1.y + q[6]*k1.z + q[7]*k1.w;
        float p = __expf(a * scale);
        se += p;
        float4 v0 = *(const float4*)&sv[j * 36 + h * DD];
        float4 v1 = *(const float4*)&sv[j * 36 + h * DD + 4];
        acc[0] += p * v0.x; acc[1] += p * v0.y; acc[2] += p * v0.z; acc[3] += p * v0.w;
        acc[4] += p * v1.x; acc[5] += p * v1.y; acc[6] += p * v1.z; acc[7] += p * v1.w;
    }
    if (jh == 1) {
        #pragma unroll
        for (int d = 0; d < DD; d++) pacc[h][lane][d] = acc[d];
        pacc[h][lane][8] = se;
    }
    __syncthreads();
    if (jh == 0) {
        se += pacc[h][lane][8];
        #pragma unroll
        for (int d = 0; d < DD; d++) acc[d] += pacc[h][lane][d];
        const float inv = 1.f / se;
        #pragma unroll
        for (int d = 0; d < DD; d++) so[lane * 33 + h * DD + d] = acc[d] * inv;
    }
    __syncthreads();

    float orow[CC];
    #pragma unroll
    for (int k = 0; k < CC; k++) orow[k] = so[lane * 33 + k];
    const int cb = h * DD + jh * 4;
    float y[4];
    float part = 0.f;
    #pragma unroll
    for (int cc = 0; cc < 4; cc++) {
        const int c = cb + cc;
        float a = sbo[c];
        #pragma unroll
        for (int k = 0; k < CC; k++) a += orow[k] * sWout[c * CC + k];
        const float x = sval_i * sew[c] + seb[c] + spos[lane * 33 + c];
        y[cc] = a + x;
        part += y[cc];
    }
    pmu[w][lane] = part;
    __syncthreads();
    float mu = 0.f;
    #pragma unroll
    for (int t = 0; t < 8; t++) mu += pmu[t][lane];
    mu *= (1.f / CC);
    float vp = 0.f;
    #pragma unroll
    for (int cc = 0; cc < 4; cc++) { float d = y[cc] - mu; vp += d * d; }
    pvar[w][lane] = vp;
    __syncthreads();
    float var = 0.f;
    #pragma unroll
    for (int t = 0; t < 8; t++) var += pvar[t][lane];
    var *= (1.f / CC);
    const float rs = rsqrtf(var + LN_EPS);

    float4 o4;
    o4.x = (y[0] - mu) * rs * sg[cb + 0] + sb2[cb + 0];
    o4.y = (y[1] - mu) * rs * sg[cb + 1] + sb2[cb + 1];
    o4.z = (y[2] - mu) * rs * sg[cb + 2] + sb2[cb + 2];
    o4.w = (y[3] - mu) * rs * sg[cb + 3] + sb2[cb + 3];
    *(float4*)&g_xbuf[((b * LL + i) * SS + s) * CC + cb] = o4;
}

// ---------------------------------------------------------------------------
// Kernel 2: column MHA (seq=4) + LN + mean over S.
// grid = B*8 = 512 (8 l's/block), block = 256
// ---------------------------------------------------------------------------
__global__ __launch_bounds__(256)
void k_col_attn(const float* __restrict__ Win,  const float* __restrict__ bin,
                const float* __restrict__ Wout, const float* __restrict__ bout,
                const float* __restrict__ lng,  const float* __restrict__ lnb)
{
    __shared__ float sx[32 * 33];
    __shared__ float sk[32 * 33];
    __shared__ float sv[32 * 33];
    __shared__ float so[32 * 33];
    __shared__ float sWin[96 * CC];
    __shared__ float sWout[CC * CC];
    __shared__ float sbin[96];
    __shared__ float sbo[CC], sg[CC], sb2[CC];
    __shared__ float pmu[8][32], pvar[8][32];

    const int blk = blockIdx.x;
    const int b = blk >> 3;
    const int lg = blk & 7;
    const int tid = threadIdx.x;
    const int w = tid >> 5;
    const int tk = tid & 31;
    const int h = w & 3;
    const int sp = w >> 2;

    const int gb = (b * 64 + lg * 8) * SS * CC;
    for (int t = tid; t < 1024; t += 256)
        sx[(t >> 5) * 33 + (t & 31)] = g_xbuf[gb + t];
    for (int t = tid; t < 96 * CC; t += 256) sWin[t] = Win[t];
    for (int t = tid; t < CC * CC; t += 256) sWout[t] = Wout[t];
    if (tid < 96) sbin[tid] = bin[tid];
    if (tid < CC) { sbo[tid] = bout[tid]; sg[tid] = lng[tid]; sb2[tid] = lnb[tid]; }
    __syncthreads();

    float xr[CC];
    #pragma unroll
    for (int c = 0; c < CC; c++) xr[c] = sx[tk * 33 + c];

    float q[DD];
    if (sp == 0) {
        #pragma unroll
        for (int d = 0; d < DD; d++) {
            const int r = h * DD + d;
            float a = sbin[r];
            #pragma unroll
            for (int c = 0; c < CC; c++) a += xr[c] * sWin[r * CC + c];
            q[d] = a;
        }
    } else {
        #pragma unroll
        for (int d = 0; d < DD; d++) {
            const int r = CC + h * DD + d;
            float a = sbin[r];
            #pragma unroll
            for (int c = 0; c < CC; c++) a += xr[c] * sWin[r * CC + c];
            sk[tk * 33 + h * DD + d] = a;
        }
        #pragma unroll
        for (int d = 0; d < DD; d++) {
            const int r = 2 * CC + h * DD + d;
            float a = sbin[r];
            #pragma unroll
            for (int c = 0; c < CC; c++) a += xr[c] * sWin[r * CC + c];
            sv[tk * 33 + h * DD + d] = a;
        }
    }
    __syncthreads();

    if (sp == 0) {
        const float scale = 0.3535533905932738f;
        const int base = tk & ~3;
        float se = 0.f;
        float acc[DD];
        #pragma unroll
        for (int d = 0; d < DD; d++) acc[d] = 0.f;
        #pragma unroll
        for (int j = 0; j < SS; j++) {
            float a = 0.f;
            #pragma unroll
            for (int d = 0; d < DD; d++) a += q[d] * sk[(base + j) * 33 + h * DD + d];
            float p = __expf(a * scale);
            se += p;
            #pragma unroll
            for (int d = 0; d < DD; d++) acc[d] += p * sv[(base + j) * 33 + h * DD + d];
        }
        const float inv = 1.f / se;
        #pragma unroll
        for (int d = 0; d < DD; d++) so[tk * 33 + h * DD + d] = acc[d] * inv;
    }
    __syncthreads();

    float orow[CC];
    #pragma unroll
    for (int k = 0; k < CC; k++) orow[k] = so[tk * 33 + k];
    const int cb = h * DD + sp * 4;
    float y[4];
    float part = 0.f;
    #pragma unroll
    for (int cc = 0; cc < 4; cc++) {
        const int c = cb + cc;
        float a = sbo[c];
        #pragma unroll
        for (int k = 0; k < CC; k++) a += orow[k] * sWout[c * CC + k];
        y[cc] = a + sx[tk * 33 + c];
        part += y[cc];
    }
    pmu[w][tk] = part;
    __syncthreads();
    float mu = 0.f;
    #pragma unroll
    for (int t = 0; t < 8; t++) mu += pmu[t][tk];
    mu *= (1.f / CC);
    float vp = 0.f;
    #pragma unroll
    for (int cc = 0; cc < 4; cc++) { float d = y[cc] - mu; vp += d * d; }
    pvar[w][tk] = vp;
    __syncthreads();
    float var = 0.f;
    #pragma unroll
    for (int t = 0; t < 8; t++) var += pvar[t][tk];
    var *= (1.f / CC);
    const float rs = rsqrtf(var + LN_EPS);

    float m0[4];
    #pragma unroll
    for (int cc = 0; cc < 4; cc++) {
        float v = (y[cc] - mu) * rs * sg[cb + cc] + sb2[cb + cc];
        v += __shfl_xor_sync(0xffffffffu, v, 1);
        v += __shfl_xor_sync(0xffffffffu, v, 2);
        m0[cc] = v * 0.25f;
    }
    if ((tk & 3) == 0) {
        const int l = lg * 8 + (tk >> 2);
        *(float4*)&g_m[(b * LL + l) * CC + cb] = make_float4(m0[0], m0[1], m0[2], m0[3]);
    }
}

// ---------------------------------------------------------------------------
// Kernel 3 (fused): u = m_i^T W (register-tiled) then pair-project-LN-SiLU.
// grid = B*8 = 512 (8 i's/block), block = 256.
// Phase 1: thread owns 2 (p,c2) columns for all 8 i's: 16 FMA per 2 LDG.
// Phase 2: thread handles 2 (i,j) pairs sharing one m_j register cache.
// ---------------------------------------------------------------------------
__global__ __launch_bounds__(256)
void k_pair(const float* __restrict__ Wp, const float* __restrict__ bp,
            const float* __restrict__ png, const float* __restrict__ pnb,
            float* __restrict__ out)
{
    __shared__ float sm[LL * 33];
    __shared__ __align__(16) float su[8 * 512];
    __shared__ float snrm[LL];
    __shared__ float sbp[CPD], sg[CPD], sb[CPD];

    const int b  = blockIdx.x >> 3;
    const int ch = blockIdx.x & 7;
    const int tid = threadIdx.x;
    const int ib = ch * 8;

    for (int t = tid; t < LL * CC; t += 256)
        sm[(t >> 5) * 33 + (t & 31)] = g_m[b * (LL * CC) + t];
    if (tid < CPD) { sbp[tid] = bp[tid]; sg[tid] = png[tid]; sb[tid] = pnb[tid]; }
    __syncthreads();

    if (tid < LL) {
        float a = 0.f;
        #pragma unroll
        for (int c = 0; c < CC; c++) { float v = sm[tid * 33 + c]; a += v * v; }
        snrm[tid] = sqrtf(a);
    }

    // phase 1: pc0 = tid, pc1 = tid+256. acc[il] over all 8 block i's.
    {
        const int p0  = tid >> 5;          // 0..7
        const int c20 = tid & 31;
        float a0[8], a1[8];
        #pragma unroll
        for (int il = 0; il < 8; il++) { a0[il] = 0.f; a1[il] = 0.f; }
        #pragma unroll 8
        for (int c1 = 0; c1 < CC; c1++) {
            const float w0 = Wp[p0 * 1024 + c1 * CC + c20];
            const float w1 = Wp[(p0 + 8) * 1024 + c1 * CC + c20];
            #pragma unroll
            for (int il = 0; il < 8; il++) {
                const float mv = sm[(ib + il) * 33 + c1];   // warp-uniform broadcast
                a0[il] += mv * w0;
                a1[il] += mv * w1;
            }
        }
        #pragma unroll
        for (int il = 0; il < 8; il++) {
            su[il * 512 + tid]       = a0[il];
            su[il * 512 + 256 + tid] = a1[il];
        }
    }
    __syncthreads();

    // phase 2: thread = (il, j), handles il and il+4
    const int il0 = tid >> 6;          // 0..3 (warp-uniform)
    const int j   = tid & 63;

    float mjr[CC];
    #pragma unroll
    for (int c = 0; c < CC; c++) mjr[c] = sm[j * 33 + c];
    const float nj = snrm[j];

    #pragma unroll
    for (int half = 0; half < 2; half++) {
        const int il = il0 + half * 4;
        const int i  = ib + il;
        const float inv = 1.f / fmaxf(snrm[i] * nj, 1e-6f);

        float f[CPD];
        float mu = 0.f;
        #pragma unroll
        for (int p = 0; p < CPD; p++) {
            const float4* up = (const float4*)&su[il * 512 + p * CC];
            float a = 0.f;
            #pragma unroll
            for (int c4 = 0; c4 < 8; c4++) {
                float4 u4 = up[c4];                         // uniform broadcast
                a += u4.x * mjr[c4*4]   + u4.y * mjr[c4*4+1]
                   + u4.z * mjr[c4*4+2] + u4.w * mjr[c4*4+3];
            }
            a = a * inv + sbp[p];
            f[p] = a;
            mu += a;
        }
        mu *= (1.f / CPD);
        float var = 0.f;
        #pragma unroll
        for (int p = 0; p < CPD; p++) { float d = f[p] - mu; var += d * d; }
        var *= (1.f / CPD);
        const float rs = rsqrtf(var + LN_EPS);
        #pragma unroll
        for (int p = 0; p < CPD; p++) {
            float xn = (f[p] - mu) * rs * sg[p] + sb[p];
            float yv = xn / (1.f + __expf(-xn));
            out[((b * CPD + p) * LL + i) * LL + j] = yv;
        }
    }
}

// ---------------------------------------------------------------------------
extern "C" void kernel_launch(void* const* d_in, const int* in_sizes, int n_in,
                              void* d_out, int out_size)
{
    const float* ctcf = (const float*)d_in[0];
    const float* hac  = (const float*)d_in[1];
    const float* me1  = (const float*)d_in[2];
    const float* me3  = (const float*)d_in[3];
    const float* ew   = (const float*)d_in[4];
    const float* eb   = (const float*)d_in[5];
    const float* pos  = (const float*)d_in[6];
    const float* riw  = (const float*)d_in[7];
    const float* rib  = (const float*)d_in[8];
    const float* row_ = (const float*)d_in[9];
    const float* rob  = (const float*)d_in[10];
    const float* rlg  = (const float*)d_in[11];
    const float* rlb  = (const float*)d_in[12];
    const float* ciw  = (const float*)d_in[13];
    const float* cib  = (const float*)d_in[14];
    const float* cow  = (const float*)d_in[15];
    const float* cob  = (const float*)d_in[16];
    const float* clg  = (const float*)d_in[17];
    const float* clb  = (const float*)d_in[18];
    const float* pw   = (const float*)d_in[19];
    const float* pb   = (const float*)d_in[20];
    const float* plg  = (const float*)d_in[21];
    const float* plb  = (const float*)d_in[22];
    float* out = (float*)d_out;

    k_pre<<<96, 64>>>(riw, rib, eb, pos, ew);
    k_row_attn<<<BB * SS * 2, 256>>>(ctcf, hac, me1, me3, ew, eb, pos,
                                     row_, rob, rlg, rlb);
    k_col_attn<<<BB * 8, 256>>>(ciw, cib, cow, cob, clg, clb);
    k_pair<<<BB * 8, 256>>>(pw, pb, plg, plb, out);
}